// round 6
// baseline (speedup 1.0000x reference)
#include <cuda_runtime.h>
#include <cstddef>

// ---------------- device scratch (zero-initialized; consume-and-clear keeps it zeroed) ----------------
#define MAX_N 262144
__device__ float    g_v[128];           // proj_w @ w_st
__device__ float    g_U[16];            // user_out[b] + b_u + b_st
__device__ float    g_c;                // proj_b · w_st
__device__ float    g_delta[1 << 20];   // per-(b,n) scattered correction (4 MB)
__device__ unsigned g_flag[MAX_N];      // per-n batch bitmask

__device__ __forceinline__ float warp_sum(float p) {
    #pragma unroll
    for (int off = 16; off; off >>= 1)
        p += __shfl_xor_sync(0xffffffffu, p, off);
    return p;
}

// ---------------- K1: fused prep + corrections (validated in R4/R5, unchanged) ----------------
__global__ __launch_bounds__(256)
void k1_kernel(const int* __restrict__ now_nodes,
               const int* __restrict__ his_nodes,
               const float* __restrict__ alpha,
               const float* __restrict__ station_embedding,
               const float* __restrict__ raw_field_embed,
               const float* __restrict__ w_st,
               const float* __restrict__ w_his1,
               const float* __restrict__ b_his1,
               const float* __restrict__ w_his2,
               const float* __restrict__ b_his2,
               const float* __restrict__ proj_w,
               const float* __restrict__ proj_b,
               const float* __restrict__ w_u,
               const float* __restrict__ b_u,
               const float* __restrict__ b_st,
               const float* __restrict__ user_embedding,
               const float* __restrict__ user_emb_table,
               const float* __restrict__ theta,
               const int* __restrict__ user_id,
               int Bn, int N, int K, int BK, int hisBlocks, int nowBlocks)
{
    int tid  = threadIdx.x;
    int lane = tid & 31, warp = tid >> 5;

    if (blockIdx.x < (unsigned)hisBlocks) {
        __shared__ float w1s[128 * 64];
        __shared__ float xs[8][128];
        __shared__ float us[64];
        __shared__ float sh_bh2;

        #pragma unroll 4
        for (int i = tid; i < 128 * 64; i += 256) w1s[i] = w_his1[i];

        float4 wv = reinterpret_cast<const float4*>(w_st)[lane];
        #pragma unroll
        for (int g = 0; g < 2; ++g) {
            int r0 = warp * 8 + g * 4;
            float4 a[4];
            #pragma unroll
            for (int i = 0; i < 4; ++i)
                a[i] = reinterpret_cast<const float4*>(w_his2 + (r0 + i) * 128)[lane];
            #pragma unroll
            for (int i = 0; i < 4; ++i) {
                float p = warp_sum(a[i].x * wv.x + a[i].y * wv.y + a[i].z * wv.z + a[i].w * wv.w);
                if (lane == 0) us[r0 + i] = p;
            }
        }
        if (warp == 0) {
            float4 bh = reinterpret_cast<const float4*>(b_his2)[lane];
            float p = warp_sum(bh.x * wv.x + bh.y * wv.y + bh.z * wv.z + bh.w * wv.w);
            if (lane == 0) sh_bh2 = p;
        }
        __syncthreads();

        float b0 = b_his1[lane], b1 = b_his1[lane + 32];
        float u0 = us[lane],     u1 = us[lane + 32];
        float bh2 = sh_bh2;

        #pragma unroll
        for (int i = 0; i < 4; ++i) {
            int e = blockIdx.x * 32 + warp * 4 + i;
            if (e >= BK) break;
            int n = his_nodes[e], b = e / K;
            float4 xv = reinterpret_cast<const float4*>(
                            raw_field_embed + (size_t)n * 128)[lane];
            reinterpret_cast<float4*>(xs[warp])[lane] = xv;
            __syncwarp();
            float a0 = b0, a1 = b1;
            #pragma unroll 8
            for (int d = 0; d < 128; ++d) {
                float x = xs[warp][d];
                a0 += x * w1s[d * 64 + lane];
                a1 += x * w1s[d * 64 + lane + 32];
            }
            float l0 = a0 > 0.f ? a0 : 0.01f * a0;
            float l1 = a1 > 0.f ? a1 : 0.01f * a1;
            float val = warp_sum(l0 * u0 + l1 * u1);
            if (lane == 0) {
                atomicAdd(&g_delta[(size_t)b * N + n], alpha[n] * (val + bh2));
                atomicOr(&g_flag[n], 1u << b);
            }
            __syncwarp();
        }
    } else if (blockIdx.x < (unsigned)(hisBlocks + nowBlocks)) {
        int bb = blockIdx.x - hisBlocks;
        float4 w4 = reinterpret_cast<const float4*>(w_st)[lane];
        #pragma unroll
        for (int i = 0; i < 4; ++i) {
            int e = bb * 32 + warp * 4 + i;
            if (e >= BK) break;
            int n = now_nodes[e], b = e / K;
            float4 r = reinterpret_cast<const float4*>(
                           station_embedding + (size_t)n * 128)[lane];
            float p = warp_sum(r.x * w4.x + r.y * w4.y + r.z * w4.z + r.w * w4.w);
            if (lane == 0) {
                atomicAdd(&g_delta[(size_t)b * N + n], alpha[n] * p);
                atomicOr(&g_flag[n], 1u << b);
            }
        }
    } else {
        float4 wv = reinterpret_cast<const float4*>(w_st)[lane];
        #pragma unroll
        for (int g = 0; g < 4; ++g) {
            int r0 = warp * 16 + g * 4;
            float4 a[4];
            #pragma unroll
            for (int i = 0; i < 4; ++i)
                a[i] = reinterpret_cast<const float4*>(proj_w + (r0 + i) * 128)[lane];
            #pragma unroll
            for (int i = 0; i < 4; ++i) {
                float p = warp_sum(a[i].x * wv.x + a[i].y * wv.y + a[i].z * wv.z + a[i].w * wv.w);
                if (lane == 0) g_v[r0 + i] = p;
            }
        }
        int b = warp;
        if (b < Bn) {
            int uid = user_id[b];
            float th = theta[uid];
            float4 ue = reinterpret_cast<const float4*>(user_embedding + b * 128)[lane];
            float4 ut = reinterpret_cast<const float4*>(user_emb_table + (size_t)uid * 128)[lane];
            float4 wu = reinterpret_cast<const float4*>(w_u)[lane];
            float p = ((1.f - th) * ue.x + th * ut.x) * wu.x
                    + ((1.f - th) * ue.y + th * ut.y) * wu.y
                    + ((1.f - th) * ue.z + th * ut.z) * wu.z
                    + ((1.f - th) * ue.w + th * ut.w) * wu.w;
            p = warp_sum(p);
            if (lane == 0) g_U[b] = p + b_u[0] + b_st[0];
        }
        if (warp == 0) {
            float4 pb = reinterpret_cast<const float4*>(proj_b)[lane];
            float p = warp_sum(pb.x * wv.x + pb.y * wv.y + pb.z * wv.z + pb.w * wv.w);
            if (lane == 0) g_c = p;
        }
    }
}

// ---------------- K2: persistent warp-autonomous pipelined sweep ----------------
#define SWEEP_BLOCKS 296

__device__ __forceinline__ void load_group(const float* __restrict__ tbl,
                                           int n0, int N, int lane, float4* r)
{
    #pragma unroll
    for (int i = 0; i < 8; ++i) {
        int n = n0 + i;
        if (n < N)
            r[i] = __ldcs(reinterpret_cast<const float4*>(tbl + (size_t)n * 128) + lane);
        else
            r[i] = make_float4(0.f, 0.f, 0.f, 0.f);
    }
}

__global__ __launch_bounds__(256, 2)
void main_kernel(const float* __restrict__ set_table,
                 const float* __restrict__ alpha,
                 float* __restrict__ out, int N, int Bn)
{
    __shared__ float shS[8][8];
    int tid  = threadIdx.x;
    int lane = tid & 31, warp = tid >> 5;

    float4 v4  = reinterpret_cast<const float4*>(g_v)[lane];
    float cval = g_c;

    int ngroups     = (N + 7) >> 3;
    int total_warps = gridDim.x * 8;
    int gwarp       = blockIdx.x * 8 + warp;

    int gid = gwarp;
    if (gid >= ngroups) return;
    int n0 = gid * 8;

    float4 cur[8];
    load_group(set_table, n0, N, lane, cur);

    for (;;) {
        int gnext = gid + total_warps;
        bool has_next = gnext < ngroups;
        float4 nxt[8];
        if (has_next)
            load_group(set_table, gnext * 8, N, lane, nxt);   // in flight during compute

        // ---- reduce current group ----
        #pragma unroll
        for (int i = 0; i < 8; ++i) {
            float p = warp_sum(cur[i].x * v4.x + cur[i].y * v4.y
                             + cur[i].z * v4.z + cur[i].w * v4.w);
            if (lane == 0) shS[warp][i] = p + cval;
        }
        __syncwarp();

        // ---- flags ----
        unsigned fl = 0;
        int nj = n0 + lane;
        if (lane < 8 && nj < N) fl = g_flag[nj];

        // ---- writes: Bn*8 outputs, 32 lanes per iter ----
        for (int idx = lane; idx < Bn * 8; idx += 32) {
            int b = idx >> 3, j = idx & 7, n = n0 + j;
            unsigned f = __shfl_sync(0xffffffffu, fl, j);
            if (n < N) {
                float s  = shS[warp][j];
                float Ub = g_U[b];
                float val = s + Ub;
                if ((f >> b) & 1u) {
                    val = (1.f - alpha[n]) * s + Ub + g_delta[(size_t)b * N + n];
                    g_delta[(size_t)b * N + n] = 0.f;      // restore zero for next replay
                }
                out[(size_t)b * N + n] = val;
            }
        }
        if (lane < 8 && nj < N && fl) g_flag[nj] = 0u;     // restore zero for next replay
        __syncwarp();

        if (!has_next) break;
        gid = gnext; n0 = gid * 8;
        #pragma unroll
        for (int i = 0; i < 8; ++i) cur[i] = nxt[i];
    }
}

// ---------------- host launch ----------------
extern "C" void kernel_launch(void* const* d_in, const int* in_sizes, int n_in,
                              void* d_out, int out_size)
{
    int iUE, iSE, iRFE, iHIS, iNOW, iUID, iUET, iSET, iPW, iPB, iTH, iAL,
        iW1, iB1, iW2, iB2, iWST, iBST, iWU, iBU;
    if (in_sizes[3] < 100000) {
        iUE=0; iSE=1; iRFE=2; iHIS=3; iNOW=4; iUID=5; iUET=6; iSET=7; iPW=8; iPB=9;
        iTH=10; iAL=11; iW1=12; iB1=13; iW2=14; iB2=15; iWST=16; iBST=17; iWU=18; iBU=19;
    } else {
        iUE=0; iSE=1; iRFE=2; iUET=3; iSET=4; iPW=5; iPB=6; iTH=7; iAL=8; iW1=9;
        iB1=10; iW2=11; iB2=12; iWST=13; iBST=14; iWU=15; iBU=16; iHIS=17; iNOW=18; iUID=19;
    }

    const float* user_embedding    = (const float*)d_in[iUE];
    const float* station_embedding = (const float*)d_in[iSE];
    const float* raw_field_embed   = (const float*)d_in[iRFE];
    const float* user_emb_table    = (const float*)d_in[iUET];
    const float* station_emb_table = (const float*)d_in[iSET];
    const float* proj_w            = (const float*)d_in[iPW];
    const float* proj_b            = (const float*)d_in[iPB];
    const float* theta             = (const float*)d_in[iTH];
    const float* alpha             = (const float*)d_in[iAL];
    const float* w_his1            = (const float*)d_in[iW1];
    const float* b_his1            = (const float*)d_in[iB1];
    const float* w_his2            = (const float*)d_in[iW2];
    const float* b_his2            = (const float*)d_in[iB2];
    const float* w_st              = (const float*)d_in[iWST];
    const float* b_st              = (const float*)d_in[iBST];
    const float* w_u               = (const float*)d_in[iWU];
    const float* b_u               = (const float*)d_in[iBU];
    const int*   his_nodes         = (const int*)d_in[iHIS];
    const int*   now_nodes         = (const int*)d_in[iNOW];
    const int*   user_id           = (const int*)d_in[iUID];

    int B  = in_sizes[iUE] / 128;     // 8
    int N  = in_sizes[iAL];           // 60082
    int BK = in_sizes[iHIS];          // 256
    int K  = BK / B;                  // 32

    float* out = (float*)d_out;
    (void)out_size; (void)n_in;

    int hisBlocks = (BK + 31) / 32;
    int nowBlocks = (BK + 31) / 32;
    k1_kernel<<<hisBlocks + nowBlocks + 1, 256>>>(
        now_nodes, his_nodes, alpha, station_embedding, raw_field_embed,
        w_st, w_his1, b_his1, w_his2, b_his2, proj_w, proj_b,
        w_u, b_u, b_st, user_embedding, user_emb_table, theta, user_id,
        B, N, K, BK, hisBlocks, nowBlocks);

    main_kernel<<<SWEEP_BLOCKS, 256>>>(station_emb_table, alpha, out, N, B);
}